// round 2
// baseline (speedup 1.0000x reference)
#include <cuda_runtime.h>
#include <math.h>

#define D_MODEL   1024
#define D_EXPERT  512
#define N_EXPERTS 8
#define N_TOKENS  8192            // B*S = 4*2048
#define OUT_ELEMS (N_TOKENS * D_MODEL)

#define BM 64                     // tokens per tile
#define BK 32                     // k-chunk
#define MOE_THREADS 512

// ---------------- scratch (no allocations allowed) ----------------
__device__ float g_cnorm[N_EXPERTS * D_MODEL];
__device__ int   g_counts[N_EXPERTS];
__device__ int   g_tok [N_EXPERTS * N_TOKENS];
__device__ float g_gate[N_EXPERTS * N_TOKENS];

// ---------------- packed f32x2 helpers (Blackwell FFMA2) ----------------
__device__ __forceinline__ unsigned long long pack2(float a, float b) {
    unsigned long long r;
    asm("mov.b64 %0, {%1, %2};" : "=l"(r) : "f"(a), "f"(b));
    return r;
}
__device__ __forceinline__ unsigned long long fma2(unsigned long long a,
                                                   unsigned long long b,
                                                   unsigned long long c) {
    unsigned long long d;
    asm("fma.rn.f32x2 %0, %1, %2, %3;" : "=l"(d) : "l"(a), "l"(b), "l"(c));
    return d;
}
__device__ __forceinline__ float2 unpack2(unsigned long long v) {
    float2 f;
    asm("mov.b64 {%0, %1}, %2;" : "=f"(f.x), "=f"(f.y) : "l"(v));
    return f;
}

__device__ __forceinline__ float gelu_exact(float v) {
    return 0.5f * v * (1.0f + erff(v * 0.70710678118654752f));
}

// ---------------- kernel 1: normalize centroids + zero counts ----------------
__global__ void prep_kernel(const float* __restrict__ centroids) {
    int w = threadIdx.x >> 5;      // 8 warps, one per expert
    int lane = threadIdx.x & 31;
    if (threadIdx.x < N_EXPERTS) g_counts[threadIdx.x] = 0;
    const float* c = centroids + w * D_MODEL;
    float v[32];
    float ss = 0.f;
#pragma unroll
    for (int i = 0; i < 32; i++) { v[i] = c[lane + 32 * i]; ss += v[i] * v[i]; }
#pragma unroll
    for (int o = 16; o > 0; o >>= 1) ss += __shfl_xor_sync(0xffffffffu, ss, o);
    float inv = 1.f / fmaxf(sqrtf(ss), 1e-12f);
    float* dst = g_cnorm + w * D_MODEL;
#pragma unroll
    for (int i = 0; i < 32; i++) dst[lane + 32 * i] = v[i] * inv;
}

// ---------------- kernel 2: routing (one warp per token) ----------------
__global__ void route_kernel(const float* __restrict__ x,
                             const float* __restrict__ w_route) {
    int t = blockIdx.x * 8 + (threadIdx.x >> 5);
    int lane = threadIdx.x & 31;
    const float* xr = x + (size_t)t * D_MODEL;

    float xv[32];
    float ss = 0.f;
#pragma unroll
    for (int i = 0; i < 32; i++) { xv[i] = xr[lane + 32 * i]; ss += xv[i] * xv[i]; }
#pragma unroll
    for (int o = 16; o > 0; o >>= 1) ss += __shfl_xor_sync(0xffffffffu, ss, o);
    float inv_norm = 1.f / fmaxf(sqrtf(ss), 1e-12f);

    float logits[N_EXPERTS];
#pragma unroll
    for (int e = 0; e < N_EXPERTS; e++) {
        const float* c  = g_cnorm + e * D_MODEL;
        const float* wr = w_route + e * D_MODEL;
        float dc = 0.f, dr = 0.f;
#pragma unroll
        for (int i = 0; i < 32; i++) {
            float xi = xv[i];
            dc += xi * c [lane + 32 * i];
            dr += xi * wr[lane + 32 * i];
        }
#pragma unroll
        for (int o = 16; o > 0; o >>= 1) {
            dc += __shfl_xor_sync(0xffffffffu, dc, o);
            dr += __shfl_xor_sync(0xffffffffu, dr, o);
        }
        logits[e] = dc * inv_norm + dr;
    }

    // top-2 (ties: first index wins, matching lax.top_k ordering)
    int i0 = 0; float v0 = logits[0];
#pragma unroll
    for (int e = 1; e < N_EXPERTS; e++)
        if (logits[e] > v0) { v0 = logits[e]; i0 = e; }
    int i1 = -1; float v1 = -1e30f;
#pragma unroll
    for (int e = 0; e < N_EXPERTS; e++)
        if (e != i0 && logits[e] > v1) { v1 = logits[e]; i1 = e; }

    float e1 = expf(v1 - v0);
    float g0 = 1.f / (1.f + e1);
    float g1 = e1 / (1.f + e1);

    if (lane == 0) {
        int p0 = atomicAdd(&g_counts[i0], 1);
        g_tok [i0 * N_TOKENS + p0] = t;
        g_gate[i0 * N_TOKENS + p0] = g0;
        int p1 = atomicAdd(&g_counts[i1], 1);
        g_tok [i1 * N_TOKENS + p1] = t;
        g_gate[i1 * N_TOKENS + p1] = g1;
    }
}

// ---------------- kernel 3: grouped expert FFN ----------------
// SMEM: Hs[64][512] | Ws[32][512] | Xs[64][32] | stok[64] | sgate[64]
#define SMEM_FLOATS (BM * D_EXPERT + BK * D_EXPERT + BM * BK + BM + BM)
#define SMEM_BYTES  (SMEM_FLOATS * 4)

__global__ void __launch_bounds__(MOE_THREADS, 1)
moe_kernel(const float* __restrict__ x,
           const float* __restrict__ w1, const float* __restrict__ b1,
           const float* __restrict__ w2, const float* __restrict__ b2,
           float* __restrict__ out) {
    int e = blockIdx.y;
    int cnt = g_counts[e];
    int m0 = blockIdx.x * BM;
    if (m0 >= cnt) return;

    extern __shared__ float smem[];
    float* Hs = smem;                       // 64*512
    float* Ws = Hs + BM * D_EXPERT;         // 32*512
    float* Xs = Ws + BK * D_EXPERT;         // 64*32
    int*   stok  = (int*)(Xs + BM * BK);    // 64
    float* sgate = (float*)(stok + BM);     // 64

    int tid = threadIdx.x;
    int tn = tid & 63;                      // 64 n-groups
    int tm = tid >> 6;                      // 8 m-groups

    if (tid < BM) {
        int g = m0 + tid;
        bool ok = (g < cnt);
        stok [tid] = ok ? g_tok [e * N_TOKENS + g] : -1;
        sgate[tid] = ok ? g_gate[e * N_TOKENS + g] : 0.f;
    }
    __syncthreads();

    unsigned long long acc[8][4];
#pragma unroll
    for (int i = 0; i < 8; i++)
#pragma unroll
        for (int j = 0; j < 4; j++) acc[i][j] = 0ull;

    const float* w1e = w1 + (size_t)e * D_MODEL * D_EXPERT;

    // ---------- phase 1: H = gelu(X @ W1 + b1) ----------
    for (int kc = 0; kc < D_MODEL; kc += BK) {
        {   // stage X tile (gathered rows)
            int m  = tid >> 3;
            int k4 = (tid & 7) * 4;
            int tok = stok[m];
            float4 v = make_float4(0.f, 0.f, 0.f, 0.f);
            if (tok >= 0) v = *(const float4*)(x + (size_t)tok * D_MODEL + kc + k4);
            *(float4*)&Xs[m * BK + k4] = v;
        }
#pragma unroll
        for (int i = 0; i < 8; i++) {       // stage W1 chunk [32][512]
            int idx = tid + i * MOE_THREADS;
            int row = idx >> 7;
            int c4  = (idx & 127) * 4;
            *(float4*)&Ws[row * D_EXPERT + c4] =
                *(const float4*)(w1e + (size_t)(kc + row) * D_EXPERT + c4);
        }
        __syncthreads();
#pragma unroll 8
        for (int kk = 0; kk < BK; kk++) {
            unsigned long long xp[8];
#pragma unroll
            for (int i = 0; i < 8; i++) {
                float xv = Xs[(tm * 8 + i) * BK + kk];
                xp[i] = pack2(xv, xv);
            }
#pragma unroll
            for (int j = 0; j < 4; j++) {
                unsigned long long wv =
                    *(const unsigned long long*)&Ws[kk * D_EXPERT + 2 * (tn + 64 * j)];
#pragma unroll
                for (int i = 0; i < 8; i++) acc[i][j] = fma2(xp[i], wv, acc[i][j]);
            }
        }
        __syncthreads();
    }

    const float* b1e = b1 + e * D_EXPERT;
#pragma unroll
    for (int i = 0; i < 8; i++) {
        int m = tm * 8 + i;
#pragma unroll
        for (int j = 0; j < 4; j++) {
            int c = 2 * (tn + 64 * j);
            float2 a = unpack2(acc[i][j]);
            Hs[m * D_EXPERT + c]     = gelu_exact(a.x + b1e[c]);
            Hs[m * D_EXPERT + c + 1] = gelu_exact(a.y + b1e[c + 1]);
        }
    }
    __syncthreads();

    // ---------- phase 2: O = (H @ W2 + b2) * gate, atomic accumulate ----------
    const float* w2e = w2 + (size_t)e * D_EXPERT * D_MODEL;
    const float* b2e = b2 + e * D_MODEL;

    for (int half = 0; half < 2; half++) {
#pragma unroll
        for (int i = 0; i < 8; i++)
#pragma unroll
            for (int j = 0; j < 4; j++) acc[i][j] = 0ull;

        for (int kc = 0; kc < D_EXPERT; kc += BK) {
            __syncthreads();                // Ws reuse protection
#pragma unroll
            for (int i = 0; i < 8; i++) {   // stage W2 chunk [32][512]
                int idx = tid + i * MOE_THREADS;
                int row = idx >> 7;
                int c4  = (idx & 127) * 4;
                *(float4*)&Ws[row * D_EXPERT + c4] =
                    *(const float4*)(w2e + (size_t)(kc + row) * D_MODEL
                                     + half * D_EXPERT + c4);
            }
            __syncthreads();
#pragma unroll 8
            for (int kk = 0; kk < BK; kk++) {
                unsigned long long hp[8];
#pragma unroll
                for (int i = 0; i < 8; i++) {
                    float hv = Hs[(tm * 8 + i) * D_EXPERT + kc + kk];
                    hp[i] = pack2(hv, hv);
                }
#pragma unroll
                for (int j = 0; j < 4; j++) {
                    unsigned long long wv =
                        *(const unsigned long long*)&Ws[kk * D_EXPERT + 2 * (tn + 64 * j)];
#pragma unroll
                    for (int i = 0; i < 8; i++) acc[i][j] = fma2(hp[i], wv, acc[i][j]);
                }
            }
        }

#pragma unroll
        for (int i = 0; i < 8; i++) {
            int m = tm * 8 + i;
            int tok = stok[m];
            if (tok < 0) continue;
            float g = sgate[m];
            float* orow = out + (size_t)tok * D_MODEL + half * D_EXPERT;
#pragma unroll
            for (int j = 0; j < 4; j++) {
                int c = 2 * (tn + 64 * j);
                float2 a = unpack2(acc[i][j]);
                atomicAdd(&orow[c],     (a.x + b2e[half * D_EXPERT + c])     * g);
                atomicAdd(&orow[c + 1], (a.y + b2e[half * D_EXPERT + c + 1]) * g);
            }
        }
    }
}

// ---------------- launch ----------------
extern "C" void kernel_launch(void* const* d_in, const int* in_sizes, int n_in,
                              void* d_out, int out_size) {
    const float* x    = (const float*)d_in[0];
    const float* w1   = (const float*)d_in[1];
    const float* b1   = (const float*)d_in[2];
    const float* w2   = (const float*)d_in[3];
    const float* b2   = (const float*)d_in[4];
    const float* cent = (const float*)d_in[5];
    const float* wrt  = (const float*)d_in[6];
    float* out = (float*)d_out;

    cudaMemsetAsync(out, 0, (size_t)OUT_ELEMS * sizeof(float));
    prep_kernel<<<1, 256>>>(cent);
    route_kernel<<<N_TOKENS / 8, 256>>>(x, wrt);

    cudaFuncSetAttribute(moe_kernel,
                         cudaFuncAttributeMaxDynamicSharedMemorySize, SMEM_BYTES);
    dim3 grid(N_TOKENS / BM, N_EXPERTS);   // 128 tiles x 8 experts, inactive tiles exit
    moe_kernel<<<grid, MOE_THREADS, SMEM_BYTES>>>(x, w1, b1, w2, b2, out);
}

// round 6
// speedup vs baseline: 2.0716x; 2.0716x over previous
#include <cuda_runtime.h>
#include <cuda_bf16.h>
#include <math.h>
#include <stdint.h>

#define D_MODEL   1024
#define D_EXPERT  512
#define N_EXPERTS 8
#define N_TOKENS  8192
#define TILE_M    128
#define NSLOT     (2 * N_TOKENS + TILE_M)

__device__ float g_cnorm[N_EXPERTS * D_MODEL];
__device__ int   g_counts[N_EXPERTS];
__device__ int   g_off[N_EXPERTS + 1];
__device__ int   g_tok[N_EXPERTS * N_TOKENS];
__device__ int   g_texp[2 * N_TOKENS];
__device__ int   g_tpos[2 * N_TOKENS];
__device__ float g_tgate[2 * N_TOKENS];
__device__ __align__(256) __nv_bfloat16 g_xhi[N_TOKENS * D_MODEL];
__device__ __align__(256) __nv_bfloat16 g_xlo[N_TOKENS * D_MODEL];
__device__ __align__(256) __nv_bfloat16 g_w1hi[N_EXPERTS * D_EXPERT * D_MODEL];
__device__ __align__(256) __nv_bfloat16 g_w1lo[N_EXPERTS * D_EXPERT * D_MODEL];
__device__ __align__(256) __nv_bfloat16 g_w2hi[N_EXPERTS * D_MODEL * D_EXPERT];
__device__ __align__(256) __nv_bfloat16 g_w2lo[N_EXPERTS * D_MODEL * D_EXPERT];
__device__ __align__(256) __nv_bfloat16 g_hhi[(size_t)NSLOT * D_EXPERT];
__device__ __align__(256) __nv_bfloat16 g_hlo[(size_t)NSLOT * D_EXPERT];
__device__ __align__(256) float g_eout[(size_t)NSLOT * D_MODEL];

__device__ __forceinline__ uint32_t smem_u32(const void* p) {
    uint32_t a;
    asm("{ .reg .u64 t; cvta.to.shared.u64 t, %1; cvt.u32.u64 %0, t; }" : "=r"(a) : "l"(p));
    return a;
}
__device__ __forceinline__ void cpa(uint32_t dst, const void* src) {
    asm volatile("cp.async.cg.shared.global [%0], [%1], 16;" :: "r"(dst), "l"(src));
}
#define CP_COMMIT() asm volatile("cp.async.commit_group;" ::: "memory")
#define CP_WAIT(n)  asm volatile("cp.async.wait_group %0;" :: "n"(n) : "memory")

__device__ __forceinline__ void stcg32(void* p, uint32_t v) {
    asm volatile("st.global.cg.b32 [%0], %1;" :: "l"(p), "r"(v) : "memory");
}
__device__ __forceinline__ void mma_bf16(float* d, const uint32_t* a, const uint32_t* b) {
    asm volatile("mma.sync.aligned.m16n8k16.row.col.f32.bf16.bf16.f32 "
                 "{%0,%1,%2,%3}, {%4,%5,%6,%7}, {%8,%9}, {%0,%1,%2,%3};"
                 : "+f"(d[0]), "+f"(d[1]), "+f"(d[2]), "+f"(d[3])
                 : "r"(a[0]), "r"(a[1]), "r"(a[2]), "r"(a[3]), "r"(b[0]), "r"(b[1]));
}
__device__ __forceinline__ float gelu_exact(float v) {
    return 0.5f * v * (1.0f + erff(v * 0.70710678118654752f));
}
__device__ __forceinline__ uint32_t pack_split(float a, float b, uint32_t* lo) {
    __nv_bfloat16 h0 = __float2bfloat16(a), h1 = __float2bfloat16(b);
    __nv_bfloat16 l0 = __float2bfloat16(a - __bfloat162float(h0));
    __nv_bfloat16 l1 = __float2bfloat16(b - __bfloat162float(h1));
    *lo = (uint32_t)__bfloat16_as_ushort(l0) | ((uint32_t)__bfloat16_as_ushort(l1) << 16);
    return (uint32_t)__bfloat16_as_ushort(h0) | ((uint32_t)__bfloat16_as_ushort(h1) << 16);
}

// ---------------- aux kernels ----------------
__global__ void prep_kernel(const float* __restrict__ centroids) {
    int w = threadIdx.x >> 5, lane = threadIdx.x & 31;
    if (threadIdx.x < N_EXPERTS) g_counts[threadIdx.x] = 0;
    const float* c = centroids + w * D_MODEL;
    float v[32], ss = 0.f;
#pragma unroll
    for (int i = 0; i < 32; i++) { v[i] = c[lane + 32 * i]; ss += v[i] * v[i]; }
#pragma unroll
    for (int o = 16; o > 0; o >>= 1) ss += __shfl_xor_sync(~0u, ss, o);
    float inv = 1.f / fmaxf(sqrtf(ss), 1e-12f);
    float* dst = g_cnorm + w * D_MODEL;
#pragma unroll
    for (int i = 0; i < 32; i++) dst[lane + 32 * i] = v[i] * inv;
}

__global__ void xsplit_kernel(const float* __restrict__ x) {
    size_t i = (size_t)blockIdx.x * blockDim.x + threadIdx.x;   // one float4
    const float4 v = ((const float4*)x)[i];
    uint32_t l0, l1;
    uint32_t h0 = pack_split(v.x, v.y, &l0);
    uint32_t h1 = pack_split(v.z, v.w, &l1);
    ((uint2*)g_xhi)[i] = make_uint2(h0, h1);
    ((uint2*)g_xlo)[i] = make_uint2(l0, l1);
}

// transpose [k=R][n=C] -> [n][k] with bf16 split
__global__ void wconv_kernel(const float* __restrict__ src, __nv_bfloat16* __restrict__ hi,
                             __nv_bfloat16* __restrict__ lo, int R, int C) {
    __shared__ float t[32][33];
    int e = blockIdx.z, c0 = blockIdx.x * 32, r0 = blockIdx.y * 32;
    int xx = threadIdx.x, yy = threadIdx.y;
    const float* s = src + (size_t)e * R * C;
#pragma unroll
    for (int k = 0; k < 4; k++) t[yy + 8 * k][xx] = s[(size_t)(r0 + yy + 8 * k) * C + c0 + xx];
    __syncthreads();
#pragma unroll
    for (int k = 0; k < 4; k++) {
        float v = t[xx][yy + 8 * k];
        __nv_bfloat16 h = __float2bfloat16(v);
        size_t o = (size_t)e * R * C + (size_t)(c0 + yy + 8 * k) * R + r0 + xx;
        hi[o] = h;
        lo[o] = __float2bfloat16(v - __bfloat162float(h));
    }
}

__global__ void route_kernel(const float* __restrict__ x, const float* __restrict__ w_route) {
    int t = blockIdx.x * 8 + (threadIdx.x >> 5);
    int lane = threadIdx.x & 31;
    const float* xr = x + (size_t)t * D_MODEL;
    float xv[32], ss = 0.f;
#pragma unroll
    for (int i = 0; i < 32; i++) { xv[i] = xr[lane + 32 * i]; ss += xv[i] * xv[i]; }
#pragma unroll
    for (int o = 16; o > 0; o >>= 1) ss += __shfl_xor_sync(~0u, ss, o);
    float inv_norm = 1.f / fmaxf(sqrtf(ss), 1e-12f);
    float logits[N_EXPERTS];
#pragma unroll
    for (int e = 0; e < N_EXPERTS; e++) {
        const float* c = g_cnorm + e * D_MODEL;
        const float* wr = w_route + e * D_MODEL;
        float dc = 0.f, dr = 0.f;
#pragma unroll
        for (int i = 0; i < 32; i++) { dc += xv[i] * c[lane + 32 * i]; dr += xv[i] * wr[lane + 32 * i]; }
#pragma unroll
        for (int o = 16; o > 0; o >>= 1) { dc += __shfl_xor_sync(~0u, dc, o); dr += __shfl_xor_sync(~0u, dr, o); }
        logits[e] = dc * inv_norm + dr;
    }
    int i0 = 0; float v0 = logits[0];
#pragma unroll
    for (int e = 1; e < N_EXPERTS; e++) if (logits[e] > v0) { v0 = logits[e]; i0 = e; }
    int i1 = -1; float v1 = -1e30f;
#pragma unroll
    for (int e = 0; e < N_EXPERTS; e++) if (e != i0 && logits[e] > v1) { v1 = logits[e]; i1 = e; }
    float e1 = expf(v1 - v0), g0 = 1.f / (1.f + e1), g1 = e1 / (1.f + e1);
    if (lane == 0) {
        int p0 = atomicAdd(&g_counts[i0], 1);
        g_tok[i0 * N_TOKENS + p0] = t;
        g_texp[t] = i0; g_tpos[t] = p0; g_tgate[t] = g0;
        int p1 = atomicAdd(&g_counts[i1], 1);
        g_tok[i1 * N_TOKENS + p1] = t;
        g_texp[N_TOKENS + t] = i1; g_tpos[N_TOKENS + t] = p1; g_tgate[N_TOKENS + t] = g1;
    }
}

__global__ void scan_kernel() {
    if (threadIdx.x == 0) {
        int a = 0;
        for (int e = 0; e < N_EXPERTS; e++) { g_off[e] = a; a += g_counts[e]; }
        g_off[N_EXPERTS] = a;
    }
}

// ---------------- MoE FFN on HMMA (mma.sync bf16, 3-term split) ----------------
// SMEM: stok[128] @0 | two buffers @1024: [Xhi 18432 | Xlo | Whi | Wlo] each 73728
#define SSTRIDE 144            // bytes per 64-elem bf16 row (72 elems, 16B-aligned pad)
#define ABYTES  18432          // 128 * SSTRIDE
#define BUFBYTES (4 * ABYTES)
#define SMEM_BYTES (1024 + 2 * BUFBYTES)

__device__ __forceinline__ void compute64(float acc[2][8][4],
                                          const char* Xh, const char* Xl,
                                          const char* Wh, const char* Wl,
                                          int wm, int wn, int gid, int tig) {
#pragma unroll
    for (int kk = 0; kk < 4; kk++) {
        int k0 = kk * 16;
        uint32_t ah[2][4], al[2][4];
#pragma unroll
        for (int mf = 0; mf < 2; mf++) {
            int off = (wm * 32 + mf * 16 + gid) * SSTRIDE + (k0 + 2 * tig) * 2;
            ah[mf][0] = *(const uint32_t*)(Xh + off);
            ah[mf][1] = *(const uint32_t*)(Xh + off + 8 * SSTRIDE);
            ah[mf][2] = *(const uint32_t*)(Xh + off + 16);
            ah[mf][3] = *(const uint32_t*)(Xh + off + 8 * SSTRIDE + 16);
            al[mf][0] = *(const uint32_t*)(Xl + off);
            al[mf][1] = *(const uint32_t*)(Xl + off + 8 * SSTRIDE);
            al[mf][2] = *(const uint32_t*)(Xl + off + 16);
            al[mf][3] = *(const uint32_t*)(Xl + off + 8 * SSTRIDE + 16);
        }
#pragma unroll
        for (int nf = 0; nf < 8; nf++) {
            int off = (wn * 64 + nf * 8 + gid) * SSTRIDE + (k0 + 2 * tig) * 2;
            uint32_t bh[2] = { *(const uint32_t*)(Wh + off), *(const uint32_t*)(Wh + off + 16) };
            uint32_t bl[2] = { *(const uint32_t*)(Wl + off), *(const uint32_t*)(Wl + off + 16) };
#pragma unroll
            for (int mf = 0; mf < 2; mf++) {
                mma_bf16(acc[mf][nf], ah[mf], bh);
                mma_bf16(acc[mf][nf], ah[mf], bl);
                mma_bf16(acc[mf][nf], al[mf], bh);
            }
        }
    }
}

__global__ void __launch_bounds__(256, 1)
moe_kernel(const float* __restrict__ b1, const float* __restrict__ b2) {
    int e = blockIdx.y;
    int cnt = g_counts[e];
    int m0 = blockIdx.x * TILE_M;
    if (m0 >= cnt) return;
    int valid = min(TILE_M, cnt - m0);
    int sb = g_off[e] + m0;

    extern __shared__ char smem[];
    int* stok = (int*)smem;
    uint32_t sbase = smem_u32(smem);
    int tid = threadIdx.x, wid = tid >> 5, lane = tid & 31;
    int gid = lane >> 2, tig = lane & 3;
    int wm = wid >> 1, wn = wid & 1;

    if (tid < TILE_M) {
        int g = m0 + tid;
        stok[tid] = (g < cnt) ? g_tok[e * N_TOKENS + g] : 0;
    }
    __syncthreads();

    float acc[2][8][4];

    // ======== PHASE 1: H = gelu(X @ W1^T + b1) ; N=512 in 4 blocks ========
    for (int nb = 0; nb < 4; nb++) {
#pragma unroll
        for (int mf = 0; mf < 2; mf++)
#pragma unroll
            for (int nf = 0; nf < 8; nf++)
#pragma unroll
                for (int q = 0; q < 4; q++) acc[mf][nf][q] = 0.f;

        const int NCH = D_MODEL / 64;   // 16
        for (int pc = 0; pc <= NCH; pc++) {
            if (pc < NCH) {             // stage chunk pc into buffer pc&1
                int buf = pc & 1;
                uint32_t dbase = sbase + 1024 + buf * BUFBYTES;
#pragma unroll
                for (int i = 0; i < 8; i++) {   // X: 2048 cp.async
                    int idx = tid + i * 256;
                    int row = idx >> 4, sub = idx & 15, half = sub >> 3, j = sub & 7;
                    const __nv_bfloat16* s = (half ? g_xlo : g_xhi) +
                        (size_t)stok[row] * D_MODEL + pc * 64 + j * 8;
                    cpa(dbase + half * ABYTES + row * SSTRIDE + j * 16, s);
                }
#pragma unroll
                for (int i = 0; i < 8; i++) {   // W1 rows nb*128..+128
                    int idx = tid + i * 256;
                    int row = idx >> 4, sub = idx & 15, half = sub >> 3, j = sub & 7;
                    const __nv_bfloat16* s = (half ? g_w1lo : g_w1hi) +
                        ((size_t)e * D_EXPERT + nb * 128 + row) * D_MODEL + pc * 64 + j * 8;
                    cpa(dbase + (2 + half) * ABYTES + row * SSTRIDE + j * 16, s);
                }
                CP_COMMIT();
            }
            if (pc > 0) {               // compute chunk pc-1
                if (pc < NCH) { CP_WAIT(1); } else { CP_WAIT(0); }
                __syncthreads();
                const char* b = smem + 1024 + ((pc - 1) & 1) * BUFBYTES;
                compute64(acc, b, b + ABYTES, b + 2 * ABYTES, b + 3 * ABYTES, wm, wn, gid, tig);
                __syncthreads();
            }
        }
        // epilogue: bias + gelu + split -> g_hhi/g_hlo (L2-only stores)
        const float* b1e = b1 + e * D_EXPERT + nb * 128;
#pragma unroll
        for (int mf = 0; mf < 2; mf++) {
            int r0 = wm * 32 + mf * 16 + gid;
#pragma unroll
            for (int nf = 0; nf < 8; nf++) {
                int col = wn * 64 + nf * 8 + 2 * tig;
                float bb0 = b1e[col], bb1 = b1e[col + 1];
                float h0 = gelu_exact(acc[mf][nf][0] + bb0);
                float h1 = gelu_exact(acc[mf][nf][1] + bb1);
                float h2 = gelu_exact(acc[mf][nf][2] + bb0);
                float h3 = gelu_exact(acc[mf][nf][3] + bb1);
                uint32_t lo, hi;
                size_t base = (size_t)(sb + r0) * D_EXPERT + nb * 128 + col;
                if (r0 < valid) {
                    hi = pack_split(h0, h1, &lo);
                    stcg32((char*)g_hhi + base * 2, hi);
                    stcg32((char*)g_hlo + base * 2, lo);
                }
                if (r0 + 8 < valid) {
                    size_t base8 = base + (size_t)8 * D_EXPERT;
                    hi = pack_split(h2, h3, &lo);
                    stcg32((char*)g_hhi + base8 * 2, hi);
                    stcg32((char*)g_hlo + base8 * 2, lo);
                }
            }
        }
        __syncthreads();
    }

    // ======== PHASE 2: eout = H @ W2^T + b2 ; N=1024 in 8 blocks ========
    for (int nb = 0; nb < 8; nb++) {
#pragma unroll
        for (int mf = 0; mf < 2; mf++)
#pragma unroll
            for (int nf = 0; nf < 8; nf++)
#pragma unroll
                for (int q = 0; q < 4; q++) acc[mf][nf][q] = 0.f;

        const int NCH = D_EXPERT / 64;  // 8
        for (int pc = 0; pc <= NCH; pc++) {
            if (pc < NCH) {
                int buf = pc & 1;
                uint32_t dbase = sbase + 1024 + buf * BUFBYTES;
#pragma unroll
                for (int i = 0; i < 8; i++) {   // H rows (contiguous slots)
                    int idx = tid + i * 256;
                    int row = idx >> 4, sub = idx & 15, half = sub >> 3, j = sub & 7;
                    const __nv_bfloat16* s = (half ? g_hlo : g_hhi) +
                        (size_t)(sb + row) * D_EXPERT + pc * 64 + j * 8;
                    cpa(dbase + half * ABYTES + row * SSTRIDE + j * 16, s);
                }
#pragma unroll
                for (int i = 0; i < 8; i++) {   // W2 rows nb*128..+128
                    int idx = tid + i * 256;
                    int row = idx >> 4, sub = idx & 15, half = sub >> 3, j = sub & 7;
                    const __nv_bfloat16* s = (half ? g_w2lo : g_w2hi) +
                        ((size_t)e * D_MODEL + nb * 128 + row) * D_EXPERT + pc * 64 + j * 8;
                    cpa(dbase + (2 + half) * ABYTES + row * SSTRIDE + j * 16, s);
                }
                CP_COMMIT();
            }
            if (pc > 0) {
                if (pc < NCH) { CP_WAIT(1); } else { CP_WAIT(0); }
                __syncthreads();
                const char* b = smem + 1024 + ((pc - 1) & 1) * BUFBYTES;
                compute64(acc, b, b + ABYTES, b + 2 * ABYTES, b + 3 * ABYTES, wm, wn, gid, tig);
                __syncthreads();
            }
        }
        // epilogue: + b2 -> g_eout
        const float* b2e = b2 + e * D_MODEL + nb * 128;
#pragma unroll
        for (int mf = 0; mf < 2; mf++) {
            int r0 = wm * 32 + mf * 16 + gid;
#pragma unroll
            for (int nf = 0; nf < 8; nf++) {
                int col = wn * 64 + nf * 8 + 2 * tig;
                float bb0 = b2e[col], bb1 = b2e[col + 1];
                if (r0 < valid) {
                    float2 v = make_float2(acc[mf][nf][0] + bb0, acc[mf][nf][1] + bb1);
                    *(float2*)(g_eout + (size_t)(sb + r0) * D_MODEL + nb * 128 + col) = v;
                }
                if (r0 + 8 < valid) {
                    float2 v = make_float2(acc[mf][nf][2] + bb0, acc[mf][nf][3] + bb1);
                    *(float2*)(g_eout + (size_t)(sb + r0 + 8) * D_MODEL + nb * 128 + col) = v;
                }
            }
        }
        __syncthreads();
    }
}

__global__ void combine_kernel(float* __restrict__ out) {
    int t = blockIdx.x, c = threadIdx.x * 4;
    int s0 = g_off[g_texp[t]] + g_tpos[t];
    int s1 = g_off[g_texp[N_TOKENS + t]] + g_tpos[N_TOKENS + t];
    float g0 = g_tgate[t], g1 = g_tgate[N_TOKENS + t];
    float4 a = *(const float4*)(g_eout + (size_t)s0 * D_MODEL + c);
    float4 b = *(const float4*)(g_eout + (size_t)s1 * D_MODEL + c);
    float4 r;
    r.x = g0 * a.x + g1 * b.x; r.y = g0 * a.y + g1 * b.y;
    r.z = g0 * a.z + g1 * b.z; r.w = g0 * a.w + g1 * b.w;
    *(float4*)(out + (size_t)t * D_MODEL + c) = r;
}

extern "C" void kernel_launch(void* const* d_in, const int* in_sizes, int n_in,
                              void* d_out, int out_size) {
    const float* x    = (const float*)d_in[0];
    const float* w1   = (const float*)d_in[1];
    const float* b1   = (const float*)d_in[2];
    const float* w2   = (const float*)d_in[3];
    const float* b2   = (const float*)d_in[4];
    const float* cent = (const float*)d_in[5];
    const float* wrt  = (const float*)d_in[6];
    float* out = (float*)d_out;

    prep_kernel<<<1, 256>>>(cent);
    xsplit_kernel<<<(N_TOKENS * D_MODEL / 4) / 256, 256>>>(x);
    __nv_bfloat16 *w1hi, *w1lo, *w2hi, *w2lo;
    cudaGetSymbolAddress((void**)&w1hi, g_w1hi);
    cudaGetSymbolAddress((void**)&w1lo, g_w1lo);
    cudaGetSymbolAddress((void**)&w2hi, g_w2hi);
    cudaGetSymbolAddress((void**)&w2lo, g_w2lo);
    dim3 tb(32, 8);
    wconv_kernel<<<dim3(D_EXPERT / 32, D_MODEL / 32, N_EXPERTS), tb>>>(w1, w1hi, w1lo, D_MODEL, D_EXPERT);
    wconv_kernel<<<dim3(D_MODEL / 32, D_EXPERT / 32, N_EXPERTS), tb>>>(w2, w2hi, w2lo, D_EXPERT, D_MODEL);
    route_kernel<<<N_TOKENS / 8, 256>>>(x, wrt);
    scan_kernel<<<1, 32>>>();

    cudaFuncSetAttribute(moe_kernel, cudaFuncAttributeMaxDynamicSharedMemorySize, SMEM_BYTES);
    moe_kernel<<<dim3(N_TOKENS / TILE_M, N_EXPERTS), 256, SMEM_BYTES>>>(b1, b2);
    combine_kernel<<<N_TOKENS, 256>>>(out);
}